// round 1
// baseline (speedup 1.0000x reference)
#include <cuda_runtime.h>
#include <math.h>

// Problem constants (fixed by the benchmark's setup_inputs)
#define T_TOK 2048   // B*S tokens
#define H_DIM 2048
#define I_DIM 1024
#define N_EXP 16
#define TOPK  4
#define NGRP  4
#define GSZ   4      // experts per group
#define SCALING 2.5f

// ---------------------------------------------------------------------------
// Scratch (device globals — no allocation allowed)
// ---------------------------------------------------------------------------
__device__ int   d_counts[N_EXP];
__device__ int   d_tok[N_EXP][T_TOK];
__device__ float d_wgt[N_EXP][T_TOK];
__device__ float d_h1 [N_EXP][T_TOK][I_DIM];   // per-expert SwiGLU hidden (134 MB)
__device__ float d_h1s[T_TOK][I_DIM];          // shared-expert hidden (8 MB)

// ---------------------------------------------------------------------------
// Zero per-expert counters (must run each replay; graph-capturable)
// ---------------------------------------------------------------------------
__global__ void zero_counts_kernel() {
    if (threadIdx.x < N_EXP) d_counts[threadIdx.x] = 0;
}

// ---------------------------------------------------------------------------
// Routing: logits -> sigmoid -> group top-2-sum -> top-2 groups -> top-4
// experts -> normalized weights * SCALING. Builds per-expert token lists.
// One block per token, 256 threads (16 threads per expert for the dot).
// ---------------------------------------------------------------------------
__global__ __launch_bounds__(256) void route_kernel(
    const float* __restrict__ x,        // [T, H]
    const float* __restrict__ gw,       // [E, H]
    const float* __restrict__ bias)     // [E]
{
    __shared__ float xs[H_DIM];
    __shared__ float logits[N_EXP];

    const int t = blockIdx.x;
    const float* xr = x + (size_t)t * H_DIM;
    for (int i = threadIdx.x; i < H_DIM; i += blockDim.x) xs[i] = xr[i];
    __syncthreads();

    const int e    = threadIdx.x >> 4;   // 0..15
    const int lane = threadIdx.x & 15;
    const float* g = gw + (size_t)e * H_DIM;
    float s = 0.f;
    for (int k = lane; k < H_DIM; k += 16) s += xs[k] * g[k];
    #pragma unroll
    for (int o = 8; o > 0; o >>= 1) s += __shfl_down_sync(0xffffffffu, s, o, 16);
    if (lane == 0) logits[e] = s;
    __syncthreads();

    if (threadIdx.x == 0) {
        float sc[N_EXP], bs[N_EXP];
        #pragma unroll
        for (int i = 0; i < N_EXP; i++) {
            sc[i] = 1.f / (1.f + expf(-logits[i]));
            bs[i] = sc[i] + bias[i];
        }
        // group score = sum of top-2 biased scores within the group
        float gsc[NGRP];
        #pragma unroll
        for (int gi = 0; gi < NGRP; gi++) {
            float m1 = -1e30f, m2 = -1e30f;
            #pragma unroll
            for (int j = 0; j < GSZ; j++) {
                float v = bs[gi * GSZ + j];
                if (v > m1) { m2 = m1; m1 = v; } else if (v > m2) { m2 = v; }
            }
            gsc[gi] = m1 + m2;
        }
        // top-2 groups (ties -> lower index, matching jax top_k)
        int g1 = 0;
        for (int gi = 1; gi < NGRP; gi++) if (gsc[gi] > gsc[g1]) g1 = gi;
        int g2 = -1;
        for (int gi = 0; gi < NGRP; gi++) {
            if (gi == g1) continue;
            if (g2 < 0 || gsc[gi] > gsc[g2]) g2 = gi;
        }
        bool allowed[N_EXP], used[N_EXP];
        #pragma unroll
        for (int i = 0; i < N_EXP; i++) {
            int gi = i / GSZ;
            allowed[i] = (gi == g1 || gi == g2);
            used[i] = false;
        }
        // top-4 experts by biased score among allowed; weights from unbiased
        int sel[TOPK]; float wv[TOPK]; float wsum = 0.f;
        #pragma unroll
        for (int kk = 0; kk < TOPK; kk++) {
            int best = -1; float bv = -1e30f;
            for (int i = 0; i < N_EXP; i++) {
                if (!allowed[i] || used[i]) continue;
                if (best < 0 || bs[i] > bv) { best = i; bv = bs[i]; }
            }
            used[best] = true; sel[kk] = best; wv[kk] = sc[best]; wsum += sc[best];
        }
        const float inv = SCALING / (wsum + 1e-20f);
        #pragma unroll
        for (int kk = 0; kk < TOPK; kk++) {
            int ee   = sel[kk];
            int slot = atomicAdd(&d_counts[ee], 1);
            d_tok[ee][slot] = t;
            d_wgt[ee][slot] = wv[kk] * inv;
        }
    }
}

// ---------------------------------------------------------------------------
// GEMM1 (experts): H1[e][m][n] = silu(Xg) * (Xu) for gathered token rows.
// Tile: BM=64 tokens x BN=128 i-cols x BK=16, 256 threads, 8x4 microtile,
// two accumulator sets (gate & up).
// ---------------------------------------------------------------------------
__global__ __launch_bounds__(256) void gemm1_expert_kernel(
    const float* __restrict__ x,        // [T, H]
    const float* __restrict__ gateW,    // [E, I, H]
    const float* __restrict__ upW)      // [E, I, H]
{
    const int e  = blockIdx.z;
    const int ne = d_counts[e];
    const int m0 = blockIdx.y * 64;
    if (m0 >= ne) return;
    const int n0 = blockIdx.x * 128;

    __shared__ float As[16][64];
    __shared__ float Gs[16][128];
    __shared__ float Us[16][128];
    __shared__ int   toks[64];

    const int tid = threadIdx.x;
    if (tid < 64) {
        int r = m0 + tid;
        toks[tid] = (r < ne) ? d_tok[e][r] : d_tok[e][0];
    }
    __syncthreads();

    const float* gwp = gateW + (size_t)e * I_DIM * H_DIM;
    const float* uwp = upW   + (size_t)e * I_DIM * H_DIM;

    float cg[8][4] = {}, cu[8][4] = {};
    const int tx = tid & 31, ty = tid >> 5;

    for (int k0 = 0; k0 < H_DIM; k0 += 16) {
        #pragma unroll
        for (int i = 0; i < 4; i++) {
            int lin = tid + 256 * i;
            int m = lin >> 4, kk = lin & 15;
            As[kk][m] = x[(size_t)toks[m] * H_DIM + k0 + kk];
        }
        #pragma unroll
        for (int i = 0; i < 8; i++) {
            int lin = tid + 256 * i;
            int n = lin >> 4, kk = lin & 15;
            size_t off = (size_t)(n0 + n) * H_DIM + k0 + kk;
            Gs[kk][n] = gwp[off];
            Us[kk][n] = uwp[off];
        }
        __syncthreads();
        #pragma unroll
        for (int k = 0; k < 16; k++) {
            float4 a0 = *(const float4*)&As[k][ty * 8];
            float4 a1 = *(const float4*)&As[k][ty * 8 + 4];
            float4 gf = *(const float4*)&Gs[k][tx * 4];
            float4 uf = *(const float4*)&Us[k][tx * 4];
            float av[8] = {a0.x, a0.y, a0.z, a0.w, a1.x, a1.y, a1.z, a1.w};
            float gv[4] = {gf.x, gf.y, gf.z, gf.w};
            float uv[4] = {uf.x, uf.y, uf.z, uf.w};
            #pragma unroll
            for (int mi = 0; mi < 8; mi++)
                #pragma unroll
                for (int ni = 0; ni < 4; ni++) {
                    cg[mi][ni] += av[mi] * gv[ni];
                    cu[mi][ni] += av[mi] * uv[ni];
                }
        }
        __syncthreads();
    }

    #pragma unroll
    for (int mi = 0; mi < 8; mi++) {
        int m = m0 + ty * 8 + mi;
        float o[4];
        #pragma unroll
        for (int ni = 0; ni < 4; ni++) {
            float g = cg[mi][ni], u = cu[mi][ni];
            o[ni] = (g / (1.f + expf(-g))) * u;   // silu(g) * u
        }
        float4 hv = {o[0], o[1], o[2], o[3]};
        *(float4*)&d_h1[e][m][n0 + tx * 4] = hv;
    }
}

// ---------------------------------------------------------------------------
// GEMM1 (shared expert): identity token list over all T tokens.
// ---------------------------------------------------------------------------
__global__ __launch_bounds__(256) void gemm1_shared_kernel(
    const float* __restrict__ x,        // [T, H]
    const float* __restrict__ gateW,    // [I, H]
    const float* __restrict__ upW)      // [I, H]
{
    const int m0 = blockIdx.y * 64;
    const int n0 = blockIdx.x * 128;

    __shared__ float As[16][64];
    __shared__ float Gs[16][128];
    __shared__ float Us[16][128];

    const int tid = threadIdx.x;
    float cg[8][4] = {}, cu[8][4] = {};
    const int tx = tid & 31, ty = tid >> 5;

    for (int k0 = 0; k0 < H_DIM; k0 += 16) {
        #pragma unroll
        for (int i = 0; i < 4; i++) {
            int lin = tid + 256 * i;
            int m = lin >> 4, kk = lin & 15;
            As[kk][m] = x[(size_t)(m0 + m) * H_DIM + k0 + kk];
        }
        #pragma unroll
        for (int i = 0; i < 8; i++) {
            int lin = tid + 256 * i;
            int n = lin >> 4, kk = lin & 15;
            size_t off = (size_t)(n0 + n) * H_DIM + k0 + kk;
            Gs[kk][n] = gateW[off];
            Us[kk][n] = upW[off];
        }
        __syncthreads();
        #pragma unroll
        for (int k = 0; k < 16; k++) {
            float4 a0 = *(const float4*)&As[k][ty * 8];
            float4 a1 = *(const float4*)&As[k][ty * 8 + 4];
            float4 gf = *(const float4*)&Gs[k][tx * 4];
            float4 uf = *(const float4*)&Us[k][tx * 4];
            float av[8] = {a0.x, a0.y, a0.z, a0.w, a1.x, a1.y, a1.z, a1.w};
            float gv[4] = {gf.x, gf.y, gf.z, gf.w};
            float uv[4] = {uf.x, uf.y, uf.z, uf.w};
            #pragma unroll
            for (int mi = 0; mi < 8; mi++)
                #pragma unroll
                for (int ni = 0; ni < 4; ni++) {
                    cg[mi][ni] += av[mi] * gv[ni];
                    cu[mi][ni] += av[mi] * uv[ni];
                }
        }
        __syncthreads();
    }

    #pragma unroll
    for (int mi = 0; mi < 8; mi++) {
        int m = m0 + ty * 8 + mi;
        float o[4];
        #pragma unroll
        for (int ni = 0; ni < 4; ni++) {
            float g = cg[mi][ni], u = cu[mi][ni];
            o[ni] = (g / (1.f + expf(-g))) * u;
        }
        float4 hv = {o[0], o[1], o[2], o[3]};
        *(float4*)&d_h1s[m][n0 + tx * 4] = hv;
    }
}

// ---------------------------------------------------------------------------
// GEMM2 (shared expert): out[t][h] = H1s @ sharedDown^T. Plain stores cover
// every output element exactly once — this initializes the poisoned buffer.
// Tile: BM=64 x BN=128 x BK=16 over K=I_DIM.
// ---------------------------------------------------------------------------
__global__ __launch_bounds__(256) void gemm2_shared_kernel(
    const float* __restrict__ downW,    // [H, I]
    float* __restrict__ out)            // [T, H]
{
    const int m0 = blockIdx.y * 64;
    const int n0 = blockIdx.x * 128;

    __shared__ float As[16][64];
    __shared__ float Bs[16][128];

    const int tid = threadIdx.x;
    float c[8][4] = {};
    const int tx = tid & 31, ty = tid >> 5;

    for (int k0 = 0; k0 < I_DIM; k0 += 16) {
        #pragma unroll
        for (int i = 0; i < 4; i++) {
            int lin = tid + 256 * i;
            int m = lin >> 4, kk = lin & 15;
            As[kk][m] = d_h1s[m0 + m][k0 + kk];
        }
        #pragma unroll
        for (int i = 0; i < 8; i++) {
            int lin = tid + 256 * i;
            int n = lin >> 4, kk = lin & 15;
            Bs[kk][n] = downW[(size_t)(n0 + n) * I_DIM + k0 + kk];
        }
        __syncthreads();
        #pragma unroll
        for (int k = 0; k < 16; k++) {
            float4 a0 = *(const float4*)&As[k][ty * 8];
            float4 a1 = *(const float4*)&As[k][ty * 8 + 4];
            float4 bf = *(const float4*)&Bs[k][tx * 4];
            float av[8] = {a0.x, a0.y, a0.z, a0.w, a1.x, a1.y, a1.z, a1.w};
            float bv[4] = {bf.x, bf.y, bf.z, bf.w};
            #pragma unroll
            for (int mi = 0; mi < 8; mi++)
                #pragma unroll
                for (int ni = 0; ni < 4; ni++)
                    c[mi][ni] += av[mi] * bv[ni];
        }
        __syncthreads();
    }

    #pragma unroll
    for (int mi = 0; mi < 8; mi++) {
        int t = m0 + ty * 8 + mi;
        float4 v = {c[mi][0], c[mi][1], c[mi][2], c[mi][3]};
        *(float4*)(out + (size_t)t * H_DIM + n0 + tx * 4) = v;
    }
}

// ---------------------------------------------------------------------------
// GEMM2 (experts): Y = H1[e] @ down_e^T, scaled by routing weight, scattered
// into out with atomicAdd (tokens overlap across experts).
// ---------------------------------------------------------------------------
__global__ __launch_bounds__(256) void gemm2_expert_kernel(
    const float* __restrict__ downW,    // [E, H, I]
    float* __restrict__ out)            // [T, H]
{
    const int e  = blockIdx.z;
    const int ne = d_counts[e];
    const int m0 = blockIdx.y * 64;
    if (m0 >= ne) return;
    const int n0 = blockIdx.x * 128;

    __shared__ float As[16][64];
    __shared__ float Bs[16][128];
    __shared__ int   toks[64];
    __shared__ float wgts[64];

    const int tid = threadIdx.x;
    if (tid < 64) {
        int r = m0 + tid;
        toks[tid] = (r < ne) ? d_tok[e][r] : 0;
        wgts[tid] = (r < ne) ? d_wgt[e][r] : 0.f;
    }
    __syncthreads();

    const float* dwp = downW + (size_t)e * H_DIM * I_DIM;

    float c[8][4] = {};
    const int tx = tid & 31, ty = tid >> 5;

    for (int k0 = 0; k0 < I_DIM; k0 += 16) {
        #pragma unroll
        for (int i = 0; i < 4; i++) {
            int lin = tid + 256 * i;
            int m = lin >> 4, kk = lin & 15;
            As[kk][m] = d_h1[e][m0 + m][k0 + kk];
        }
        #pragma unroll
        for (int i = 0; i < 8; i++) {
            int lin = tid + 256 * i;
            int n = lin >> 4, kk = lin & 15;
            Bs[kk][n] = dwp[(size_t)(n0 + n) * I_DIM + k0 + kk];
        }
        __syncthreads();
        #pragma unroll
        for (int k = 0; k < 16; k++) {
            float4 a0 = *(const float4*)&As[k][ty * 8];
            float4 a1 = *(const float4*)&As[k][ty * 8 + 4];
            float4 bf = *(const float4*)&Bs[k][tx * 4];
            float av[8] = {a0.x, a0.y, a0.z, a0.w, a1.x, a1.y, a1.z, a1.w};
            float bv[4] = {bf.x, bf.y, bf.z, bf.w};
            #pragma unroll
            for (int mi = 0; mi < 8; mi++)
                #pragma unroll
                for (int ni = 0; ni < 4; ni++)
                    c[mi][ni] += av[mi] * bv[ni];
        }
        __syncthreads();
    }

    #pragma unroll
    for (int mi = 0; mi < 8; mi++) {
        int m = ty * 8 + mi;
        if (m0 + m >= ne) continue;
        int   t = toks[m];
        float w = wgts[m];
        float* op = out + (size_t)t * H_DIM + n0 + tx * 4;
        #pragma unroll
        for (int ni = 0; ni < 4; ni++)
            atomicAdd(op + ni, w * c[mi][ni]);
    }
}

// ---------------------------------------------------------------------------
// Launch: all on the default stream (sequential ordering provides the
// dependencies: zero -> route -> gemm1s -> shared-down (init out) -> expert
// down (accumulate)).
// ---------------------------------------------------------------------------
extern "C" void kernel_launch(void* const* d_in, const int* in_sizes, int n_in,
                              void* d_out, int out_size)
{
    const float* x   = (const float*)d_in[0];   // hidden_states [2,1024,2048]
    const float* gw  = (const float*)d_in[1];   // gate_weight   [16,2048]
    const float* eb  = (const float*)d_in[2];   // expert_bias   [16]
    const float* gp  = (const float*)d_in[3];   // gate_proj     [16,1024,2048]
    const float* up  = (const float*)d_in[4];   // up_proj       [16,1024,2048]
    const float* dp  = (const float*)d_in[5];   // down_proj     [16,2048,1024]
    const float* sg  = (const float*)d_in[6];   // shared_gate   [1024,2048]
    const float* su  = (const float*)d_in[7];   // shared_up     [1024,2048]
    const float* sd  = (const float*)d_in[8];   // shared_down   [2048,1024]
    float* out = (float*)d_out;

    zero_counts_kernel<<<1, 32>>>();
    route_kernel<<<T_TOK, 256>>>(x, gw, eb);

    gemm1_expert_kernel<<<dim3(I_DIM / 128, T_TOK / 64, N_EXP), 256>>>(x, gp, up);
    gemm1_shared_kernel<<<dim3(I_DIM / 128, T_TOK / 64, 1), 256>>>(x, sg, su);

    gemm2_shared_kernel<<<dim3(H_DIM / 128, T_TOK / 64, 1), 256>>>(sd, out);
    gemm2_expert_kernel<<<dim3(H_DIM / 128, T_TOK / 64, N_EXP), 256>>>(dp, out);
}

// round 3
// speedup vs baseline: 3.5093x; 3.5093x over previous
#include <cuda_runtime.h>
#include <cuda_bf16.h>
#include <stdint.h>
#include <math.h>

#define T_TOK 2048
#define H_DIM 2048
#define I_DIM 1024
#define N_EXP 16
#define TOPK  4
#define NGRP  4
#define GSZ   4
#define SCALING 2.5f

// ---------------------------------------------------------------------------
// Scratch (device globals — no allocation allowed)
// ---------------------------------------------------------------------------
__device__ int   d_counts[N_EXP];
__device__ int   d_tok[N_EXP][T_TOK];
__device__ float d_wgt[N_EXP][T_TOK];
__device__ __nv_bfloat16 d_h1_hi[N_EXP][T_TOK][I_DIM];
__device__ __nv_bfloat16 d_h1_lo[N_EXP][T_TOK][I_DIM];
__device__ __nv_bfloat16 d_h1s_hi[T_TOK][I_DIM];
__device__ __nv_bfloat16 d_h1s_lo[T_TOK][I_DIM];

// ---------------------------------------------------------------------------
// PTX helpers (baseline sm_80+ instructions only — must compile on compute_103)
// ---------------------------------------------------------------------------
__device__ __forceinline__ uint32_t smem_u32(const void* p) {
    uint32_t a;
    asm("{ .reg .u64 t; cvta.to.shared.u64 t, %1; cvt.u32.u64 %0, t; }"
        : "=r"(a) : "l"(p));
    return a;
}

__device__ __forceinline__ void ldm_x4(uint32_t addr, uint32_t r[4]) {
    asm volatile("ldmatrix.sync.aligned.m8n8.x4.shared.b16 {%0,%1,%2,%3}, [%4];"
                 : "=r"(r[0]), "=r"(r[1]), "=r"(r[2]), "=r"(r[3]) : "r"(addr));
}

__device__ __forceinline__ void mma_bf16(float d[4], const uint32_t a[4],
                                         uint32_t b0, uint32_t b1) {
    asm volatile(
        "mma.sync.aligned.m16n8k16.row.col.f32.bf16.bf16.f32 "
        "{%0,%1,%2,%3}, {%4,%5,%6,%7}, {%8,%9}, {%0,%1,%2,%3};"
        : "+f"(d[0]), "+f"(d[1]), "+f"(d[2]), "+f"(d[3])
        : "r"(a[0]), "r"(a[1]), "r"(a[2]), "r"(a[3]), "r"(b0), "r"(b1));
}

// split a float pair into packed bf16-hi word and bf16-lo (residual) word
__device__ __forceinline__ void split2(float f0, float f1, uint32_t& hw, uint32_t& lw) {
    __nv_bfloat16 h0 = __float2bfloat16_rn(f0);
    __nv_bfloat16 h1 = __float2bfloat16_rn(f1);
    __nv_bfloat16 l0 = __float2bfloat16_rn(f0 - __bfloat162float(h0));
    __nv_bfloat16 l1 = __float2bfloat16_rn(f1 - __bfloat162float(h1));
    hw = (uint32_t)__bfloat16_as_ushort(h0) | ((uint32_t)__bfloat16_as_ushort(h1) << 16);
    lw = (uint32_t)__bfloat16_as_ushort(l0) | ((uint32_t)__bfloat16_as_ushort(l1) << 16);
}

__device__ __forceinline__ void split4(float4 f, uint2& hw, uint2& lw) {
    split2(f.x, f.y, hw.x, lw.x);
    split2(f.z, f.w, hw.y, lw.y);
}

// ldmatrix source address within a padded [rows][40] bf16 tile
// rbase: first row of the 16-row block; kk: which 16-wide k-half of BK=32
__device__ __forceinline__ uint32_t ldaddr(uint32_t base, int rbase, int kk, int lane) {
    int row = rbase + (lane & 15);
    int col = kk * 16 + ((lane >> 4) << 3);
    return base + (uint32_t)((row * 40 + col) << 1);
}

// ---------------------------------------------------------------------------
// Routing (unchanged from R1 — proven correct)
// ---------------------------------------------------------------------------
__global__ void zero_counts_kernel() {
    if (threadIdx.x < N_EXP) d_counts[threadIdx.x] = 0;
}

__global__ __launch_bounds__(256) void route_kernel(
    const float* __restrict__ x, const float* __restrict__ gw,
    const float* __restrict__ bias)
{
    __shared__ float xs[H_DIM];
    __shared__ float logits[N_EXP];
    const int t = blockIdx.x;
    const float* xr = x + (size_t)t * H_DIM;
    for (int i = threadIdx.x; i < H_DIM; i += blockDim.x) xs[i] = xr[i];
    __syncthreads();

    const int e = threadIdx.x >> 4, lane = threadIdx.x & 15;
    const float* g = gw + (size_t)e * H_DIM;
    float s = 0.f;
    for (int k = lane; k < H_DIM; k += 16) s += xs[k] * g[k];
    #pragma unroll
    for (int o = 8; o > 0; o >>= 1) s += __shfl_down_sync(0xffffffffu, s, o, 16);
    if (lane == 0) logits[e] = s;
    __syncthreads();

    if (threadIdx.x == 0) {
        float sc[N_EXP], bs[N_EXP];
        #pragma unroll
        for (int i = 0; i < N_EXP; i++) {
            sc[i] = 1.f / (1.f + expf(-logits[i]));
            bs[i] = sc[i] + bias[i];
        }
        float gsc[NGRP];
        #pragma unroll
        for (int gi = 0; gi < NGRP; gi++) {
            float m1 = -1e30f, m2 = -1e30f;
            #pragma unroll
            for (int j = 0; j < GSZ; j++) {
                float v = bs[gi * GSZ + j];
                if (v > m1) { m2 = m1; m1 = v; } else if (v > m2) { m2 = v; }
            }
            gsc[gi] = m1 + m2;
        }
        int g1 = 0;
        for (int gi = 1; gi < NGRP; gi++) if (gsc[gi] > gsc[g1]) g1 = gi;
        int g2 = -1;
        for (int gi = 0; gi < NGRP; gi++) {
            if (gi == g1) continue;
            if (g2 < 0 || gsc[gi] > gsc[g2]) g2 = gi;
        }
        bool allowed[N_EXP], used[N_EXP];
        #pragma unroll
        for (int i = 0; i < N_EXP; i++) {
            int gi = i / GSZ;
            allowed[i] = (gi == g1 || gi == g2);
            used[i] = false;
        }
        int sel[TOPK]; float wv[TOPK]; float wsum = 0.f;
        #pragma unroll
        for (int kk = 0; kk < TOPK; kk++) {
            int best = -1; float bv = -1e30f;
            for (int i = 0; i < N_EXP; i++) {
                if (!allowed[i] || used[i]) continue;
                if (best < 0 || bs[i] > bv) { best = i; bv = bs[i]; }
            }
            used[best] = true; sel[kk] = best; wv[kk] = sc[best]; wsum += sc[best];
        }
        const float inv = SCALING / (wsum + 1e-20f);
        #pragma unroll
        for (int kk = 0; kk < TOPK; kk++) {
            int ee = sel[kk];
            int slot = atomicAdd(&d_counts[ee], 1);
            d_tok[ee][slot] = t;
            d_wgt[ee][slot] = wv[kk] * inv;
        }
    }
}

// ---------------------------------------------------------------------------
// GEMM1: h1 = silu(x@gate^T) * (x@up^T) for gathered tokens (bf16x3 HMMA).
// CTA tile: M=128 tokens x N=64 i-cols x K=2048, BK=32.
// 8 warps = 2(m) x 4(n); warp tile 64x16 per output (gate & up).
// Output written as bf16 hi/lo planes for GEMM2 reuse.
// ---------------------------------------------------------------------------
template<bool SHARED>
__global__ __launch_bounds__(256) void gemm1_mma(
    const float* __restrict__ x,
    const float* __restrict__ gateW,
    const float* __restrict__ upW)
{
    const int e  = SHARED ? 0 : blockIdx.z;
    const int ne = SHARED ? T_TOK : d_counts[e];
    const int m0 = blockIdx.y * 128;
    if (m0 >= ne) return;
    const int n0 = blockIdx.x * 64;

    __shared__ __align__(16) __nv_bfloat16 sAh[128][40], sAl[128][40];
    __shared__ __align__(16) __nv_bfloat16 sGh[64][40],  sGl[64][40];
    __shared__ __align__(16) __nv_bfloat16 sUh[64][40],  sUl[64][40];
    __shared__ int toks[128];

    const int tid = threadIdx.x, lane = tid & 31, wid = tid >> 5;
    const int wm = wid >> 2, wn = wid & 3;

    if (tid < 128) {
        int r = m0 + tid;
        toks[tid] = SHARED ? r : (r < ne ? d_tok[e][r] : d_tok[e][0]);
    }
    __syncthreads();

    const float* gw = gateW + (SHARED ? 0 : (size_t)e * I_DIM * H_DIM);
    const float* uw = upW   + (SHARED ? 0 : (size_t)e * I_DIM * H_DIM);

    // task decomposition for tile loads (A: 128x32 f32 as 4 float4/thr;
    // B gate/up: 64x32 f32 as 2 float4/thr each)
    int arow[4], ach[4], brow[2], bch[2];
    #pragma unroll
    for (int i = 0; i < 4; i++) { int t2 = tid + 256 * i; arow[i] = t2 >> 3; ach[i] = t2 & 7; }
    #pragma unroll
    for (int i = 0; i < 2; i++) { int t2 = tid + 256 * i; brow[i] = t2 >> 3; bch[i] = t2 & 7; }

    const uint32_t bAh = smem_u32(&sAh[0][0]), bAl = smem_u32(&sAl[0][0]);
    const uint32_t bGh = smem_u32(&sGh[0][0]), bGl = smem_u32(&sGl[0][0]);
    const uint32_t bUh = smem_u32(&sUh[0][0]), bUl = smem_u32(&sUl[0][0]);

    float cg[4][2][4] = {}, cu[4][2][4] = {};
    float4 pa[4], pg[2], pu[2];

    // preload tile 0
    #pragma unroll
    for (int i = 0; i < 4; i++)
        pa[i] = *(const float4*)(x + (size_t)toks[arow[i]] * H_DIM + ach[i] * 4);
    #pragma unroll
    for (int i = 0; i < 2; i++) {
        pg[i] = *(const float4*)(gw + (size_t)(n0 + brow[i]) * H_DIM + bch[i] * 4);
        pu[i] = *(const float4*)(uw + (size_t)(n0 + brow[i]) * H_DIM + bch[i] * 4);
    }

    const int NK = H_DIM / 32;
    for (int kt = 0; kt < NK; ++kt) {
        // convert + STS current tile
        #pragma unroll
        for (int i = 0; i < 4; i++) {
            uint2 hw, lw; split4(pa[i], hw, lw);
            *(uint2*)&sAh[arow[i]][ach[i] * 4] = hw;
            *(uint2*)&sAl[arow[i]][ach[i] * 4] = lw;
        }
        #pragma unroll
        for (int i = 0; i < 2; i++) {
            uint2 hw, lw;
            split4(pg[i], hw, lw);
            *(uint2*)&sGh[brow[i]][bch[i] * 4] = hw;
            *(uint2*)&sGl[brow[i]][bch[i] * 4] = lw;
            split4(pu[i], hw, lw);
            *(uint2*)&sUh[brow[i]][bch[i] * 4] = hw;
            *(uint2*)&sUl[brow[i]][bch[i] * 4] = lw;
        }
        __syncthreads();

        // prefetch next tile (LDG latency overlaps MMA)
        if (kt + 1 < NK) {
            const int k0 = (kt + 1) * 32;
            #pragma unroll
            for (int i = 0; i < 4; i++)
                pa[i] = *(const float4*)(x + (size_t)toks[arow[i]] * H_DIM + k0 + ach[i] * 4);
            #pragma unroll
            for (int i = 0; i < 2; i++) {
                pg[i] = *(const float4*)(gw + (size_t)(n0 + brow[i]) * H_DIM + k0 + bch[i] * 4);
                pu[i] = *(const float4*)(uw + (size_t)(n0 + brow[i]) * H_DIM + k0 + bch[i] * 4);
            }
        }

        // MMA over BK=32 (two k=16 halves)
        #pragma unroll
        for (int kk = 0; kk < 2; ++kk) {
            uint32_t ah[4][4], al[4][4];
            #pragma unroll
            for (int mi = 0; mi < 4; mi++) {
                ldm_x4(ldaddr(bAh, wm * 64 + mi * 16, kk, lane), ah[mi]);
                ldm_x4(ldaddr(bAl, wm * 64 + mi * 16, kk, lane), al[mi]);
            }
            uint32_t gh[4], gl[4], uh[4], ul[4];
            ldm_x4(ldaddr(bGh, wn * 16, kk, lane), gh);
            ldm_x4(ldaddr(bGl, wn * 16, kk, lane), gl);
            ldm_x4(ldaddr(bUh, wn * 16, kk, lane), uh);
            ldm_x4(ldaddr(bUl, wn * 16, kk, lane), ul);

            #pragma unroll
            for (int mi = 0; mi < 4; mi++)
                #pragma unroll
                for (int ni = 0; ni < 2; ni++) {
                    mma_bf16(cg[mi][ni], ah[mi], gh[ni], gh[ni + 2]);
                    mma_bf16(cg[mi][ni], ah[mi], gl[ni], gl[ni + 2]);
                    mma_bf16(cg[mi][ni], al[mi], gh[ni], gh[ni + 2]);
                    mma_bf16(cu[mi][ni], ah[mi], uh[ni], uh[ni + 2]);
                    mma_bf16(cu[mi][ni], ah[mi], ul[ni], ul[ni + 2]);
                    mma_bf16(cu[mi][ni], al[mi], uh[ni], uh[ni + 2]);
                }
        }
        __syncthreads();
    }

    // epilogue: silu(g)*u -> bf16 hi/lo planes
    const int gr = lane >> 2, tc = (lane & 3) * 2;
    __nv_bfloat16* phi = SHARED ? &d_h1s_hi[0][0] : &d_h1_hi[e][0][0];
    __nv_bfloat16* plo = SHARED ? &d_h1s_lo[0][0] : &d_h1_lo[e][0][0];

    #pragma unroll
    for (int mi = 0; mi < 4; mi++)
        #pragma unroll
        for (int ni = 0; ni < 2; ni++) {
            int ncol = n0 + wn * 16 + ni * 8 + tc;
            #pragma unroll
            for (int half = 0; half < 2; half++) {
                int m = m0 + wm * 64 + mi * 16 + gr + half * 8;
                float g0 = cg[mi][ni][half * 2],     u0 = cu[mi][ni][half * 2];
                float g1 = cg[mi][ni][half * 2 + 1], u1 = cu[mi][ni][half * 2 + 1];
                float o0 = (g0 / (1.f + expf(-g0))) * u0;
                float o1 = (g1 / (1.f + expf(-g1))) * u1;
                uint32_t hw, lw; split2(o0, o1, hw, lw);
                *(uint32_t*)(phi + (size_t)m * I_DIM + ncol) = hw;
                *(uint32_t*)(plo + (size_t)m * I_DIM + ncol) = lw;
            }
        }
}

// ---------------------------------------------------------------------------
// GEMM2: y = h1 @ down^T. A already bf16 hi/lo (no conversion).
// CTA tile: M=128 x N=128 h-cols x K=1024, BK=32.
// 8 warps = 2(m) x 4(n); warp tile 64x32.
// SHARED: plain stores (initializes out). Expert: weighted atomicAdd scatter.
// ---------------------------------------------------------------------------
template<bool SHARED>
__global__ __launch_bounds__(256) void gemm2_mma(
    const float* __restrict__ downW,
    float* __restrict__ out)
{
    const int e  = SHARED ? 0 : blockIdx.z;
    const int ne = SHARED ? T_TOK : d_counts[e];
    const int m0 = blockIdx.y * 128;
    if (m0 >= ne) return;
    const int n0 = blockIdx.x * 128;

    __shared__ __align__(16) __nv_bfloat16 sAh[128][40], sAl[128][40];
    __shared__ __align__(16) __nv_bfloat16 sBh[128][40], sBl[128][40];
    __shared__ int   toks[128];
    __shared__ float wgts[128];

    const int tid = threadIdx.x, lane = tid & 31, wid = tid >> 5;
    const int wm = wid >> 2, wn = wid & 3;

    if (!SHARED && tid < 128) {
        int r = m0 + tid;
        toks[tid] = (r < ne) ? d_tok[e][r] : 0;
        wgts[tid] = (r < ne) ? d_wgt[e][r] : 0.f;
    }
    __syncthreads();

    const __nv_bfloat16* ahi = SHARED ? &d_h1s_hi[0][0] : &d_h1_hi[e][0][0];
    const __nv_bfloat16* alo = SHARED ? &d_h1s_lo[0][0] : &d_h1_lo[e][0][0];
    const float* dw = downW + (SHARED ? 0 : (size_t)e * H_DIM * I_DIM);

    // A: 128x32 bf16 per plane, uint4 chunks (8 bf16): 512 tasks -> 2/thr
    // B: 128x32 f32, float4 chunks: 1024 tasks -> 4/thr
    int arow[2], ach[2], brow[4], bch[4];
    #pragma unroll
    for (int i = 0; i < 2; i++) { int t2 = tid + 256 * i; arow[i] = t2 >> 2; ach[i] = t2 & 3; }
    #pragma unroll
    for (int i = 0; i < 4; i++) { int t2 = tid + 256 * i; brow[i] = t2 >> 3; bch[i] = t2 & 7; }

    const uint32_t bAh = smem_u32(&sAh[0][0]), bAl = smem_u32(&sAl[0][0]);
    const uint32_t bBh = smem_u32(&sBh[0][0]), bBl = smem_u32(&sBl[0][0]);

    float cd[4][4][4] = {};
    uint4  pah[2], pal[2];
    float4 pb[4];

    #pragma unroll
    for (int i = 0; i < 2; i++) {
        size_t idx = (size_t)(m0 + arow[i]) * I_DIM + ach[i] * 8;
        pah[i] = *(const uint4*)(ahi + idx);
        pal[i] = *(const uint4*)(alo + idx);
    }
    #pragma unroll
    for (int i = 0; i < 4; i++)
        pb[i] = *(const float4*)(dw + (size_t)(n0 + brow[i]) * I_DIM + bch[i] * 4);

    const int NK = I_DIM / 32;
    for (int kt = 0; kt < NK; ++kt) {
        #pragma unroll
        for (int i = 0; i < 2; i++) {
            *(uint4*)&sAh[arow[i]][ach[i] * 8] = pah[i];
            *(uint4*)&sAl[arow[i]][ach[i] * 8] = pal[i];
        }
        #pragma unroll
        for (int i = 0; i < 4; i++) {
            uint2 hw, lw; split4(pb[i], hw, lw);
            *(uint2*)&sBh[brow[i]][bch[i] * 4] = hw;
            *(uint2*)&sBl[brow[i]][bch[i] * 4] = lw;
        }
        __syncthreads();

        if (kt + 1 < NK) {
            const int k0 = (kt + 1) * 32;
            #pragma unroll
            for (int i = 0; i < 2; i++) {
                size_t idx = (size_t)(m0 + arow[i]) * I_DIM + k0 + ach[i] * 8;
                pah[i] = *(const uint4*)(ahi + idx);
                pal[i] = *(const uint4*)(alo + idx);
            }
            #pragma unroll
            for (int i = 0; i < 4; i++)
                pb[i] = *(const float4*)(dw + (size_t)(n0 + brow[i]) * I_DIM + k0 + bch[i] * 4);
        }

        #pragma unroll
        for (int kk = 0; kk < 2; ++kk) {
            uint32_t ah[4][4], al[4][4];
            #pragma unroll
            for (int mi = 0; mi < 4; mi++) {
                ldm_x4(ldaddr(bAh, wm * 64 + mi * 16, kk, lane), ah[mi]);
                ldm_x4(ldaddr(bAl, wm * 64 + mi * 16, kk, lane), al[mi]);
            }
            uint32_t bh0[4], bh1[4], bl0[4], bl1[4];
            ldm_x4(ldaddr(bBh, wn * 32,      kk, lane), bh0);
            ldm_x4(ldaddr(bBh, wn * 32 + 16, kk, lane), bh1);
            ldm_x4(ldaddr(bBl, wn * 32,      kk, lane), bl0);
            ldm_x4(ldaddr(bBl, wn * 32 + 16, kk, lane), bl1);
            uint32_t bhs[4][2] = {{bh0[0],bh0[2]},{bh0[1],bh0[3]},{bh1[0],bh1[2]},{bh1[1],bh1[3]}};
            uint32_t bls[4][2] = {{bl0[0],bl0[2]},{bl0[1],bl0[3]},{bl1[0],bl1[2]},{bl1[1],bl1[3]}};

            #pragma unroll
            for (int mi = 0; mi < 4; mi++)
                #pragma unroll
                for (int ni = 0; ni < 4; ni++) {
                    mma_bf16(cd[mi][ni], ah[mi], bhs[ni][0], bhs[ni][1]);
                    mma_bf16(cd[mi][ni], ah[mi], bls[ni][0], bls[ni][1]);
                    mma_bf16(cd[mi][ni], al[mi], bhs[ni][0], bhs[ni][1]);
                }
        }
        __syncthreads();
    }

    // epilogue
    const int gr = lane >> 2, tc = (lane & 3) * 2;
    #pragma unroll
    for (int mi = 0; mi < 4; mi++)
        #pragma unroll
        for (int ni = 0; ni < 4; ni++) {
            int ncol = n0 + wn * 32 + ni * 8 + tc;
            #pragma unroll
            for (int half = 0; half < 2; half++) {
                int mloc = wm * 64 + mi * 16 + gr + half * 8;
                float v0 = cd[mi][ni][half * 2];
                float v1 = cd[mi][ni][half * 2 + 1];
                if (SHARED) {
                    int t = m0 + mloc;
                    float2 v = {v0, v1};
                    *(float2*)(out + (size_t)t * H_DIM + ncol) = v;
                } else {
                    if (m0 + mloc < ne) {
                        int   t = toks[mloc];
                        float w = wgts[mloc];
                        float* op = out + (size_t)t * H_DIM + ncol;
                        atomicAdd(op,     w * v0);
                        atomicAdd(op + 1, w * v1);
                    }
                }
            }
        }
}

// ---------------------------------------------------------------------------
// Launch: default stream ordering = dependencies.
// ---------------------------------------------------------------------------
extern "C" void kernel_launch(void* const* d_in, const int* in_sizes, int n_in,
                              void* d_out, int out_size)
{
    const float* x  = (const float*)d_in[0];
    const float* gw = (const float*)d_in[1];
    const float* eb = (const float*)d_in[2];
    const float* gp = (const float*)d_in[3];
    const float* up = (const float*)d_in[4];
    const float* dp = (const float*)d_in[5];
    const float* sg = (const float*)d_in[6];
    const float* su = (const float*)d_in[7];
    const float* sd = (const float*)d_in[8];
    float* out = (float*)d_out;

    zero_counts_kernel<<<1, 32>>>();
    route_kernel<<<T_TOK, 256>>>(x, gw, eb);

    gemm1_mma<false><<<dim3(I_DIM / 64, T_TOK / 128, N_EXP), 256>>>(x, gp, up);
    gemm1_mma<true> <<<dim3(I_DIM / 64, T_TOK / 128, 1),     256>>>(x, sg, su);

    gemm2_mma<true> <<<dim3(H_DIM / 128, T_TOK / 128, 1),     256>>>(sd, out);
    gemm2_mma<false><<<dim3(H_DIM / 128, T_TOK / 128, N_EXP), 256>>>(dp, out);
}

// round 4
// speedup vs baseline: 3.5224x; 1.0037x over previous
#include <cuda_runtime.h>
#include <cuda_bf16.h>
#include <stdint.h>
#include <math.h>

#define T_TOK 2048
#define H_DIM 2048
#define I_DIM 1024
#define N_EXP 16
#define TOPK  4
#define NGRP  4
#define GSZ   4
#define SCALING 2.5f

// dynamic smem: two 40960-byte pipeline stages for both GEMM kernels
#define STAGE_BYTES 40960u
#define SMEM_DYN    (2u * STAGE_BYTES)

// ---------------------------------------------------------------------------
// Scratch (device globals — no allocation allowed)
// ---------------------------------------------------------------------------
__device__ int   d_counts[N_EXP];
__device__ int   d_tok[N_EXP][T_TOK];
__device__ float d_wgt[N_EXP][T_TOK];
__device__ __nv_bfloat16 d_h1_hi[N_EXP][T_TOK][I_DIM];
__device__ __nv_bfloat16 d_h1_lo[N_EXP][T_TOK][I_DIM];
__device__ __nv_bfloat16 d_h1s_hi[T_TOK][I_DIM];
__device__ __nv_bfloat16 d_h1s_lo[T_TOK][I_DIM];

// ---------------------------------------------------------------------------
// PTX helpers (baseline sm_80+ only — must compile under compute_103)
// ---------------------------------------------------------------------------
__device__ __forceinline__ uint32_t smem_u32(const void* p) {
    uint32_t a;
    asm("{ .reg .u64 t; cvta.to.shared.u64 t, %1; cvt.u32.u64 %0, t; }"
        : "=r"(a) : "l"(p));
    return a;
}

__device__ __forceinline__ void ldm_x4(uint32_t addr, uint32_t r[4]) {
    asm volatile("ldmatrix.sync.aligned.m8n8.x4.shared.b16 {%0,%1,%2,%3}, [%4];"
                 : "=r"(r[0]), "=r"(r[1]), "=r"(r[2]), "=r"(r[3]) : "r"(addr));
}

__device__ __forceinline__ void mma_bf16(float d[4], const uint32_t a[4],
                                         uint32_t b0, uint32_t b1) {
    asm volatile(
        "mma.sync.aligned.m16n8k16.row.col.f32.bf16.bf16.f32 "
        "{%0,%1,%2,%3}, {%4,%5,%6,%7}, {%8,%9}, {%0,%1,%2,%3};"
        : "+f"(d[0]), "+f"(d[1]), "+f"(d[2]), "+f"(d[3])
        : "r"(a[0]), "r"(a[1]), "r"(a[2]), "r"(a[3]), "r"(b0), "r"(b1));
}

__device__ __forceinline__ void sts64(uint32_t addr, uint2 v) {
    asm volatile("st.shared.v2.b32 [%0], {%1,%2};"
                 :: "r"(addr), "r"(v.x), "r"(v.y) : "memory");
}
__device__ __forceinline__ void sts128(uint32_t addr, uint4 v) {
    asm volatile("st.shared.v4.b32 [%0], {%1,%2,%3,%4};"
                 :: "r"(addr), "r"(v.x), "r"(v.y), "r"(v.z), "r"(v.w) : "memory");
}

// split a float pair into packed bf16-hi word and bf16-lo (residual) word
__device__ __forceinline__ void split2(float f0, float f1, uint32_t& hw, uint32_t& lw) {
    __nv_bfloat16 h0 = __float2bfloat16_rn(f0);
    __nv_bfloat16 h1 = __float2bfloat16_rn(f1);
    __nv_bfloat16 l0 = __float2bfloat16_rn(f0 - __bfloat162float(h0));
    __nv_bfloat16 l1 = __float2bfloat16_rn(f1 - __bfloat162float(h1));
    hw = (uint32_t)__bfloat16_as_ushort(h0) | ((uint32_t)__bfloat16_as_ushort(h1) << 16);
    lw = (uint32_t)__bfloat16_as_ushort(l0) | ((uint32_t)__bfloat16_as_ushort(l1) << 16);
}

__device__ __forceinline__ void split4(float4 f, uint2& hw, uint2& lw) {
    split2(f.x, f.y, hw.x, lw.x);
    split2(f.z, f.w, hw.y, lw.y);
}

// ldmatrix source address within a padded [rows][40] bf16 plane at byte `base`
__device__ __forceinline__ uint32_t ldaddr(uint32_t base, int rbase, int kk, int lane) {
    int row = rbase + (lane & 15);
    int col = kk * 16 + ((lane >> 4) << 3);
    return base + (uint32_t)((row * 40 + col) << 1);
}

// ---------------------------------------------------------------------------
// Routing (proven)
// ---------------------------------------------------------------------------
__global__ void zero_counts_kernel() {
    if (threadIdx.x < N_EXP) d_counts[threadIdx.x] = 0;
}

__global__ __launch_bounds__(256) void route_kernel(
    const float* __restrict__ x, const float* __restrict__ gw,
    const float* __restrict__ bias)
{
    __shared__ float xs[H_DIM];
    __shared__ float logits[N_EXP];
    const int t = blockIdx.x;
    const float* xr = x + (size_t)t * H_DIM;
    for (int i = threadIdx.x; i < H_DIM; i += blockDim.x) xs[i] = xr[i];
    __syncthreads();

    const int e = threadIdx.x >> 4, lane = threadIdx.x & 15;
    const float* g = gw + (size_t)e * H_DIM;
    float s = 0.f;
    for (int k = lane; k < H_DIM; k += 16) s += xs[k] * g[k];
    #pragma unroll
    for (int o = 8; o > 0; o >>= 1) s += __shfl_down_sync(0xffffffffu, s, o, 16);
    if (lane == 0) logits[e] = s;
    __syncthreads();

    if (threadIdx.x == 0) {
        float sc[N_EXP], bs[N_EXP];
        #pragma unroll
        for (int i = 0; i < N_EXP; i++) {
            sc[i] = 1.f / (1.f + expf(-logits[i]));
            bs[i] = sc[i] + bias[i];
        }
        float gsc[NGRP];
        #pragma unroll
        for (int gi = 0; gi < NGRP; gi++) {
            float m1 = -1e30f, m2 = -1e30f;
            #pragma unroll
            for (int j = 0; j < GSZ; j++) {
                float v = bs[gi * GSZ + j];
                if (v > m1) { m2 = m1; m1 = v; } else if (v > m2) { m2 = v; }
            }
            gsc[gi] = m1 + m2;
        }
        int g1 = 0;
        for (int gi = 1; gi < NGRP; gi++) if (gsc[gi] > gsc[g1]) g1 = gi;
        int g2 = -1;
        for (int gi = 0; gi < NGRP; gi++) {
            if (gi == g1) continue;
            if (g2 < 0 || gsc[gi] > gsc[g2]) g2 = gi;
        }
        bool allowed[N_EXP], used[N_EXP];
        #pragma unroll
        for (int i = 0; i < N_EXP; i++) {
            int gi = i / GSZ;
            allowed[i] = (gi == g1 || gi == g2);
            used[i] = false;
        }
        int sel[TOPK]; float wv[TOPK]; float wsum = 0.f;
        #pragma unroll
        for (int kk = 0; kk < TOPK; kk++) {
            int best = -1; float bv = -1e30f;
            for (int i = 0; i < N_EXP; i++) {
                if (!allowed[i] || used[i]) continue;
                if (best < 0 || bs[i] > bv) { best = i; bv = bs[i]; }
            }
            used[best] = true; sel[kk] = best; wv[kk] = sc[best]; wsum += sc[best];
        }
        const float inv = SCALING / (wsum + 1e-20f);
        #pragma unroll
        for (int kk = 0; kk < TOPK; kk++) {
            int ee = sel[kk];
            int slot = atomicAdd(&d_counts[ee], 1);
            d_tok[ee][slot] = t;
            d_wgt[ee][slot] = wv[kk] * inv;
        }
    }
}

// ---------------------------------------------------------------------------
// GEMM1: h1 = silu(x@gate^T) * (x@up^T), gathered tokens, bf16x3 HMMA.
// CTA tile M=128 x N=64 x K=2048, BK=32, double-buffered smem pipeline.
// Stage layout (bytes): AH 0, AL 10240, GH 20480, GL 25600, UH 30720, UL 35840.
// ---------------------------------------------------------------------------
template<bool SHARED>
__global__ __launch_bounds__(256) void gemm1_mma(
    const float* __restrict__ x,
    const float* __restrict__ gateW,
    const float* __restrict__ upW)
{
    const int e  = SHARED ? 0 : blockIdx.z;
    const int ne = SHARED ? T_TOK : d_counts[e];
    const int m0 = blockIdx.y * 128;
    if (m0 >= ne) return;
    const int n0 = blockIdx.x * 64;

    extern __shared__ __align__(16) char dynsmem[];
    __shared__ int toks[128];

    const int tid = threadIdx.x, lane = tid & 31, wid = tid >> 5;
    const int wm = wid >> 2, wn = wid & 3;
    const uint32_t sb = smem_u32(dynsmem);

    if (tid < 128) {
        int r = m0 + tid;
        toks[tid] = SHARED ? r : (r < ne ? d_tok[e][r] : d_tok[e][0]);
    }
    __syncthreads();

    const float* gw = gateW + (SHARED ? 0 : (size_t)e * I_DIM * H_DIM);
    const float* uw = upW   + (SHARED ? 0 : (size_t)e * I_DIM * H_DIM);

    // load-task decomposition (A: 128x32 f32 -> 4 float4/thr; G/U: 64x32 -> 2 each)
    int arow[4], ach[4], brow[2], bch[2];
    uint32_t aOff[4], bOff[2];
    #pragma unroll
    for (int i = 0; i < 4; i++) {
        int t2 = tid + 256 * i; arow[i] = t2 >> 3; ach[i] = t2 & 7;
        aOff[i] = (uint32_t)(arow[i] * 80 + ach[i] * 8);
    }
    #pragma unroll
    for (int i = 0; i < 2; i++) {
        int t2 = tid + 256 * i; brow[i] = t2 >> 3; bch[i] = t2 & 7;
        bOff[i] = (uint32_t)(brow[i] * 80 + bch[i] * 8);
    }

    float cg[4][2][4] = {}, cu[4][2][4] = {};
    float4 pa[4], pg[2], pu[2];

    // preload tile 0
    #pragma unroll
    for (int i = 0; i < 4; i++)
        pa[i] = *(const float4*)(x + (size_t)toks[arow[i]] * H_DIM + ach[i] * 4);
    #pragma unroll
    for (int i = 0; i < 2; i++) {
        pg[i] = *(const float4*)(gw + (size_t)(n0 + brow[i]) * H_DIM + bch[i] * 4);
        pu[i] = *(const float4*)(uw + (size_t)(n0 + brow[i]) * H_DIM + bch[i] * 4);
    }

    // convert + store tile 0 into stage 0
    {
        const uint32_t st = sb;
        #pragma unroll
        for (int i = 0; i < 4; i++) {
            uint2 hw, lw; split4(pa[i], hw, lw);
            sts64(st + aOff[i], hw);
            sts64(st + 10240u + aOff[i], lw);
        }
        #pragma unroll
        for (int i = 0; i < 2; i++) {
            uint2 hw, lw;
            split4(pg[i], hw, lw);
            sts64(st + 20480u + bOff[i], hw);
            sts64(st + 25600u + bOff[i], lw);
            split4(pu[i], hw, lw);
            sts64(st + 30720u + bOff[i], hw);
            sts64(st + 35840u + bOff[i], lw);
        }
    }
    __syncthreads();

    const int NK = H_DIM / 32;
    #pragma unroll 1
    for (int kt = 0; kt < NK; ++kt) {
        const uint32_t cur = sb + (uint32_t)(kt & 1) * STAGE_BYTES;
        const uint32_t nxt = sb + (uint32_t)((kt + 1) & 1) * STAGE_BYTES;
        const bool more = (kt + 1 < NK);

        // prefetch next tile from gmem
        if (more) {
            const int k0 = (kt + 1) * 32;
            #pragma unroll
            for (int i = 0; i < 4; i++)
                pa[i] = *(const float4*)(x + (size_t)toks[arow[i]] * H_DIM + k0 + ach[i] * 4);
            #pragma unroll
            for (int i = 0; i < 2; i++) {
                pg[i] = *(const float4*)(gw + (size_t)(n0 + brow[i]) * H_DIM + k0 + bch[i] * 4);
                pu[i] = *(const float4*)(uw + (size_t)(n0 + brow[i]) * H_DIM + k0 + bch[i] * 4);
            }
        }

        // MMA on current stage
        const uint32_t bAh = cur, bAl = cur + 10240u;
        const uint32_t bGh = cur + 20480u, bGl = cur + 25600u;
        const uint32_t bUh = cur + 30720u, bUl = cur + 35840u;
        #pragma unroll
        for (int kk = 0; kk < 2; ++kk) {
            uint32_t ah[4][4], al[4][4];
            #pragma unroll
            for (int mi = 0; mi < 4; mi++) {
                ldm_x4(ldaddr(bAh, wm * 64 + mi * 16, kk, lane), ah[mi]);
                ldm_x4(ldaddr(bAl, wm * 64 + mi * 16, kk, lane), al[mi]);
            }
            uint32_t gh[4], gl[4], uh[4], ul[4];
            ldm_x4(ldaddr(bGh, wn * 16, kk, lane), gh);
            ldm_x4(ldaddr(bGl, wn * 16, kk, lane), gl);
            ldm_x4(ldaddr(bUh, wn * 16, kk, lane), uh);
            ldm_x4(ldaddr(bUl, wn * 16, kk, lane), ul);

            #pragma unroll
            for (int mi = 0; mi < 4; mi++)
                #pragma unroll
                for (int ni = 0; ni < 2; ni++) {
                    mma_bf16(cg[mi][ni], ah[mi], gh[ni], gh[ni + 2]);
                    mma_bf16(cg[mi][ni], ah[mi], gl[ni], gl[ni + 2]);
                    mma_bf16(cg[mi][ni], al[mi], gh[ni], gh[ni + 2]);
                    mma_bf16(cu[mi][ni], ah[mi], uh[ni], uh[ni + 2]);
                    mma_bf16(cu[mi][ni], ah[mi], ul[ni], ul[ni + 2]);
                    mma_bf16(cu[mi][ni], al[mi], uh[ni], uh[ni + 2]);
                }
        }

        // convert + store next tile into the other stage (overlaps MMA across warps)
        if (more) {
            #pragma unroll
            for (int i = 0; i < 4; i++) {
                uint2 hw, lw; split4(pa[i], hw, lw);
                sts64(nxt + aOff[i], hw);
                sts64(nxt + 10240u + aOff[i], lw);
            }
            #pragma unroll
            for (int i = 0; i < 2; i++) {
                uint2 hw, lw;
                split4(pg[i], hw, lw);
                sts64(nxt + 20480u + bOff[i], hw);
                sts64(nxt + 25600u + bOff[i], lw);
                split4(pu[i], hw, lw);
                sts64(nxt + 30720u + bOff[i], hw);
                sts64(nxt + 35840u + bOff[i], lw);
            }
        }
        __syncthreads();
    }

    // epilogue: silu(g)*u -> bf16 hi/lo planes
    const int gr = lane >> 2, tc = (lane & 3) * 2;
    __nv_bfloat16* phi = SHARED ? &d_h1s_hi[0][0] : &d_h1_hi[e][0][0];
    __nv_bfloat16* plo = SHARED ? &d_h1s_lo[0][0] : &d_h1_lo[e][0][0];

    #pragma unroll
    for (int mi = 0; mi < 4; mi++)
        #pragma unroll
        for (int ni = 0; ni < 2; ni++) {
            int ncol = n0 + wn * 16 + ni * 8 + tc;
            #pragma unroll
            for (int half = 0; half < 2; half++) {
                int m = m0 + wm * 64 + mi * 16 + gr + half * 8;
                float g0 = cg[mi][ni][half * 2],     u0 = cu[mi][ni][half * 2];
                float g1 = cg[mi][ni][half * 2 + 1], u1 = cu[mi][ni][half * 2 + 1];
                float o0 = (g0 / (1.f + expf(-g0))) * u0;
                float o1 = (g1 / (1.f + expf(-g1))) * u1;
                uint32_t hw, lw; split2(o0, o1, hw, lw);
                *(uint32_t*)(phi + (size_t)m * I_DIM + ncol) = hw;
                *(uint32_t*)(plo + (size_t)m * I_DIM + ncol) = lw;
            }
        }
}

// ---------------------------------------------------------------------------
// GEMM2: y = h1 @ down^T; A already bf16 hi/lo. Double-buffered pipeline.
// CTA tile M=128 x N=128 x K=1024, BK=32.
// Stage layout (bytes): AH 0, AL 10240, BH 20480, BL 30720.
// ---------------------------------------------------------------------------
template<bool SHARED>
__global__ __launch_bounds__(256) void gemm2_mma(
    const float* __restrict__ downW,
    float* __restrict__ out)
{
    const int e  = SHARED ? 0 : blockIdx.z;
    const int ne = SHARED ? T_TOK : d_counts[e];
    const int m0 = blockIdx.y * 128;
    if (m0 >= ne) return;
    const int n0 = blockIdx.x * 128;

    extern __shared__ __align__(16) char dynsmem[];
    __shared__ int   toks[128];
    __shared__ float wgts[128];

    const int tid = threadIdx.x, lane = tid & 31, wid = tid >> 5;
    const int wm = wid >> 2, wn = wid & 3;
    const uint32_t sb = smem_u32(dynsmem);

    if (!SHARED && tid < 128) {
        int r = m0 + tid;
        toks[tid] = (r < ne) ? d_tok[e][r] : 0;
        wgts[tid] = (r < ne) ? d_wgt[e][r] : 0.f;
    }
    __syncthreads();

    const __nv_bfloat16* ahi = SHARED ? &d_h1s_hi[0][0] : &d_h1_hi[e][0][0];
    const __nv_bfloat16* alo = SHARED ? &d_h1s_lo[0][0] : &d_h1_lo[e][0][0];
    const float* dw = downW + (SHARED ? 0 : (size_t)e * H_DIM * I_DIM);

    // A: 128x32 bf16/plane as uint4 (8 bf16): 2 tasks/thr. B: 128x32 f32: 4 tasks/thr.
    int arow[2], ach[2], brow[4], bch[4];
    uint32_t aOff[2], bOff[4];
    #pragma unroll
    for (int i = 0; i < 2; i++) {
        int t2 = tid + 256 * i; arow[i] = t2 >> 2; ach[i] = t2 & 3;
        aOff[i] = (uint32_t)(arow[i] * 80 + ach[i] * 16);
    }
    #pragma unroll
    for (int i = 0; i < 4; i++) {
        int t2 = tid + 256 * i; brow[i] = t2 >> 3; bch[i] = t2 & 7;
        bOff[i] = (uint32_t)(brow[i] * 80 + bch[i] * 8);
    }

    float cd[4][4][4] = {};
    uint4  pah[2], pal[2];
    float4 pb[4];

    #pragma unroll
    for (int i = 0; i < 2; i++) {
        size_t idx = (size_t)(m0 + arow[i]) * I_DIM + ach[i] * 8;
        pah[i] = *(const uint4*)(ahi + idx);
        pal[i] = *(const uint4*)(alo + idx);
    }
    #pragma unroll
    for (int i = 0; i < 4; i++)
        pb[i] = *(const float4*)(dw + (size_t)(n0 + brow[i]) * I_DIM + bch[i] * 4);

    {
        const uint32_t st = sb;
        #pragma unroll
        for (int i = 0; i < 2; i++) {
            sts128(st + aOff[i], pah[i]);
            sts128(st + 10240u + aOff[i], pal[i]);
        }
        #pragma unroll
        for (int i = 0; i < 4; i++) {
            uint2 hw, lw; split4(pb[i], hw, lw);
            sts64(st + 20480u + bOff[i], hw);
            sts64(st + 30720u + bOff[i], lw);
        }
    }
    __syncthreads();

    const int NK = I_DIM / 32;
    #pragma unroll 1
    for (int kt = 0; kt < NK; ++kt) {
        const uint32_t cur = sb + (uint32_t)(kt & 1) * STAGE_BYTES;
        const uint32_t nxt = sb + (uint32_t)((kt + 1) & 1) * STAGE_BYTES;
        const bool more = (kt + 1 < NK);

        if (more) {
            const int k0 = (kt + 1) * 32;
            #pragma unroll
            for (int i = 0; i < 2; i++) {
                size_t idx = (size_t)(m0 + arow[i]) * I_DIM + k0 + ach[i] * 8;
                pah[i] = *(const uint4*)(ahi + idx);
                pal[i] = *(const uint4*)(alo + idx);
            }
            #pragma unroll
            for (int i = 0; i < 4; i++)
                pb[i] = *(const float4*)(dw + (size_t)(n0 + brow[i]) * I_DIM + k0 + bch[i] * 4);
        }

        const uint32_t bAh = cur, bAl = cur + 10240u;
        const uint32_t bBh = cur + 20480u, bBl = cur + 30720u;
        #pragma unroll
        for (int kk = 0; kk < 2; ++kk) {
            uint32_t ah[4][4], al[4][4];
            #pragma unroll
            for (int mi = 0; mi < 4; mi++) {
                ldm_x4(ldaddr(bAh, wm * 64 + mi * 16, kk, lane), ah[mi]);
                ldm_x4(ldaddr(bAl, wm * 64 + mi * 16, kk, lane), al[mi]);
            }
            uint32_t bh0[4], bh1[4], bl0[4], bl1[4];
            ldm_x4(ldaddr(bBh, wn * 32,      kk, lane), bh0);
            ldm_x4(ldaddr(bBh, wn * 32 + 16, kk, lane), bh1);
            ldm_x4(ldaddr(bBl, wn * 32,      kk, lane), bl0);
            ldm_x4(ldaddr(bBl, wn * 32 + 16, kk, lane), bl1);
            uint32_t bhs[4][2] = {{bh0[0],bh0[2]},{bh0[1],bh0[3]},{bh1[0],bh1[2]},{bh1[1],bh1[3]}};
            uint32_t bls[4][2] = {{bl0[0],bl0[2]},{bl0[1],bl0[3]},{bl1[0],bl1[2]},{bl1[1],bl1[3]}};

            #pragma unroll
            for (int mi = 0; mi < 4; mi++)
                #pragma unroll
                for (int ni = 0; ni < 4; ni++) {
                    mma_bf16(cd[mi][ni], ah[mi], bhs[ni][0], bhs[ni][1]);
                    mma_bf16(cd[mi][ni], ah[mi], bls[ni][0], bls[ni][1]);
                    mma_bf16(cd[mi][ni], al[mi], bhs[ni][0], bhs[ni][1]);
                }
        }

        if (more) {
            #pragma unroll
            for (int i = 0; i < 2; i++) {
                sts128(nxt + aOff[i], pah[i]);
                sts128(nxt + 10240u + aOff[i], pal[i]);
            }
            #pragma unroll
            for (int i = 0; i < 4; i++) {
                uint2 hw, lw; split4(pb[i], hw, lw);
                sts64(nxt + 20480u + bOff[i], hw);
                sts64(nxt + 30720u + bOff[i], lw);
            }
        }
        __syncthreads();
    }

    // epilogue
    const int gr = lane >> 2, tc = (lane & 3) * 2;
    #pragma unroll
    for (int mi = 0; mi < 4; mi++)
        #pragma unroll
        for (int ni = 0; ni < 4; ni++) {
            int ncol = n0 + wn * 32 + ni * 8 + tc;
            #pragma unroll
            for (int half = 0; half < 2; half++) {
                int mloc = wm * 64 + mi * 16 + gr + half * 8;
                float v0 = cd[mi][ni][half * 2];
                float v1 = cd[mi][ni][half * 2 + 1];
                if (SHARED) {
                    int t = m0 + mloc;
                    float2 v = {v0, v1};
                    *(float2*)(out + (size_t)t * H_DIM + ncol) = v;
                } else {
                    if (m0 + mloc < ne) {
                        int   t = toks[mloc];
                        float w = wgts[mloc];
                        float* op = out + (size_t)t * H_DIM + ncol;
                        atomicAdd(op,     w * v0);
                        atomicAdd(op + 1, w * v1);
                    }
                }
            }
        }
}

// ---------------------------------------------------------------------------
// Launch
// ---------------------------------------------------------------------------
extern "C" void kernel_launch(void* const* d_in, const int* in_sizes, int n_in,
                              void* d_out, int out_size)
{
    const float* x  = (const float*)d_in[0];
    const float* gw = (const float*)d_in[1];
    const float* eb = (const float*)d_in[2];
    const float* gp = (const float*)d_in[3];
    const float* up = (const float*)d_in[4];
    const float* dp = (const float*)d_in[5];
    const float* sg = (const float*)d_in[6];
    const float* su = (const float*)d_in[7];
    const float* sd = (const float*)d_in[8];
    float* out = (float*)d_out;

    static bool attr_set = false;
    if (!attr_set) {
        cudaFuncSetAttribute((const void*)gemm1_mma<false>, cudaFuncAttributeMaxDynamicSharedMemorySize, SMEM_DYN);
        cudaFuncSetAttribute((const void*)gemm1_mma<true>,  cudaFuncAttributeMaxDynamicSharedMemorySize, SMEM_DYN);
        cudaFuncSetAttribute((const void*)gemm2_mma<false>, cudaFuncAttributeMaxDynamicSharedMemorySize, SMEM_DYN);
        cudaFuncSetAttribute((const void*)gemm2_mma<true>,  cudaFuncAttributeMaxDynamicSharedMemorySize, SMEM_DYN);
        attr_set = true;
    }

    zero_counts_kernel<<<1, 32>>>();
    route_kernel<<<T_TOK, 256>>>(x, gw, eb);

    gemm1_mma<false><<<dim3(I_DIM / 64, T_TOK / 128, N_EXP), 256, SMEM_DYN>>>(x, gp, up);
    gemm1_mma<true> <<<dim3(I_DIM / 64, T_TOK / 128, 1),     256, SMEM_DYN>>>(x, sg, su);

    gemm2_mma<true> <<<dim3(H_DIM / 128, T_TOK / 128, 1),     256, SMEM_DYN>>>(sd, out);
    gemm2_mma<false><<<dim3(H_DIM / 128, T_TOK / 128, N_EXP), 256, SMEM_DYN>>>(dp, out);
}

// round 5
// speedup vs baseline: 3.8563x; 1.0948x over previous
#include <cuda_runtime.h>
#include <cuda_bf16.h>
#include <stdint.h>
#include <math.h>

#define T_TOK 2048
#define H_DIM 2048
#define I_DIM 1024
#define N_EXP 16
#define TOPK  4
#define NGRP  4
#define GSZ   4
#define SCALING 2.5f

#define STAGE_BYTES 40960u
#define SMEM_DYN    (2u * STAGE_BYTES)

// ---------------------------------------------------------------------------
// Scratch (device globals)
// ---------------------------------------------------------------------------
__device__ int   d_counts[N_EXP];
__device__ int   d_tok[N_EXP][T_TOK];
__device__ float d_wgt[N_EXP][T_TOK];
__device__ __nv_bfloat16 d_h1_hi[N_EXP][T_TOK][I_DIM];
__device__ __nv_bfloat16 d_h1_lo[N_EXP][T_TOK][I_DIM];
__device__ __nv_bfloat16 d_h1s_hi[T_TOK][I_DIM];
__device__ __nv_bfloat16 d_h1s_lo[T_TOK][I_DIM];

// ---------------------------------------------------------------------------
// PTX helpers (baseline sm_80+ only)
// ---------------------------------------------------------------------------
__device__ __forceinline__ uint32_t smem_u32(const void* p) {
    uint32_t a;
    asm("{ .reg .u64 t; cvta.to.shared.u64 t, %1; cvt.u32.u64 %0, t; }"
        : "=r"(a) : "l"(p));
    return a;
}

__device__ __forceinline__ void ldm_x4(uint32_t addr, uint32_t r[4]) {
    asm volatile("ldmatrix.sync.aligned.m8n8.x4.shared.b16 {%0,%1,%2,%3}, [%4];"
                 : "=r"(r[0]), "=r"(r[1]), "=r"(r[2]), "=r"(r[3]) : "r"(addr));
}

__device__ __forceinline__ void mma_bf16(float d[4], const uint32_t a[4],
                                         uint32_t b0, uint32_t b1) {
    asm volatile(
        "mma.sync.aligned.m16n8k16.row.col.f32.bf16.bf16.f32 "
        "{%0,%1,%2,%3}, {%4,%5,%6,%7}, {%8,%9}, {%0,%1,%2,%3};"
        : "+f"(d[0]), "+f"(d[1]), "+f"(d[2]), "+f"(d[3])
        : "r"(a[0]), "r"(a[1]), "r"(a[2]), "r"(a[3]), "r"(b0), "r"(b1));
}

__device__ __forceinline__ void sts64(uint32_t addr, uint2 v) {
    asm volatile("st.shared.v2.b32 [%0], {%1,%2};"
                 :: "r"(addr), "r"(v.x), "r"(v.y) : "memory");
}
__device__ __forceinline__ void sts128(uint32_t addr, uint4 v) {
    asm volatile("st.shared.v4.b32 [%0], {%1,%2,%3,%4};"
                 :: "r"(addr), "r"(v.x), "r"(v.y), "r"(v.z), "r"(v.w) : "memory");
}

__device__ __forceinline__ void split2(float f0, float f1, uint32_t& hw, uint32_t& lw) {
    __nv_bfloat16 h0 = __float2bfloat16_rn(f0);
    __nv_bfloat16 h1 = __float2bfloat16_rn(f1);
    __nv_bfloat16 l0 = __float2bfloat16_rn(f0 - __bfloat162float(h0));
    __nv_bfloat16 l1 = __float2bfloat16_rn(f1 - __bfloat162float(h1));
    hw = (uint32_t)__bfloat16_as_ushort(h0) | ((uint32_t)__bfloat16_as_ushort(h1) << 16);
    lw = (uint32_t)__bfloat16_as_ushort(l0) | ((uint32_t)__bfloat16_as_ushort(l1) << 16);
}

__device__ __forceinline__ void split4(float4 f, uint2& hw, uint2& lw) {
    split2(f.x, f.y, hw.x, lw.x);
    split2(f.z, f.w, hw.y, lw.y);
}

// stage-relative ldmatrix offset for padded [rows][40] bf16 plane
__device__ __forceinline__ uint32_t ldrel(uint32_t plane, int rbase, int lane) {
    int row = rbase + (lane & 15);
    int col = (lane >> 4) << 3;
    return plane + (uint32_t)((row * 40 + col) << 1);
}

// ---------------------------------------------------------------------------
// Routing (proven)
// ---------------------------------------------------------------------------
__global__ void zero_counts_kernel() {
    if (threadIdx.x < N_EXP) d_counts[threadIdx.x] = 0;
}

__global__ __launch_bounds__(256) void route_kernel(
    const float* __restrict__ x, const float* __restrict__ gw,
    const float* __restrict__ bias)
{
    __shared__ float xs[H_DIM];
    __shared__ float logits[N_EXP];
    const int t = blockIdx.x;
    const float* xr = x + (size_t)t * H_DIM;
    for (int i = threadIdx.x; i < H_DIM; i += blockDim.x) xs[i] = xr[i];
    __syncthreads();

    const int e = threadIdx.x >> 4, lane = threadIdx.x & 15;
    const float* g = gw + (size_t)e * H_DIM;
    float s = 0.f;
    for (int k = lane; k < H_DIM; k += 16) s += xs[k] * g[k];
    #pragma unroll
    for (int o = 8; o > 0; o >>= 1) s += __shfl_down_sync(0xffffffffu, s, o, 16);
    if (lane == 0) logits[e] = s;
    __syncthreads();

    if (threadIdx.x == 0) {
        float sc[N_EXP], bs[N_EXP];
        #pragma unroll
        for (int i = 0; i < N_EXP; i++) {
            sc[i] = 1.f / (1.f + expf(-logits[i]));
            bs[i] = sc[i] + bias[i];
        }
        float gsc[NGRP];
        #pragma unroll
        for (int gi = 0; gi < NGRP; gi++) {
            float m1 = -1e30f, m2 = -1e30f;
            #pragma unroll
            for (int j = 0; j < GSZ; j++) {
                float v = bs[gi * GSZ + j];
                if (v > m1) { m2 = m1; m1 = v; } else if (v > m2) { m2 = v; }
            }
            gsc[gi] = m1 + m2;
        }
        int g1 = 0;
        for (int gi = 1; gi < NGRP; gi++) if (gsc[gi] > gsc[g1]) g1 = gi;
        int g2 = -1;
        for (int gi = 0; gi < NGRP; gi++) {
            if (gi == g1) continue;
            if (g2 < 0 || gsc[gi] > gsc[g2]) g2 = gi;
        }
        bool allowed[N_EXP], used[N_EXP];
        #pragma unroll
        for (int i = 0; i < N_EXP; i++) {
            int gi = i / GSZ;
            allowed[i] = (gi == g1 || gi == g2);
            used[i] = false;
        }
        int sel[TOPK]; float wv[TOPK]; float wsum = 0.f;
        #pragma unroll
        for (int kk = 0; kk < TOPK; kk++) {
            int best = -1; float bv = -1e30f;
            for (int i = 0; i < N_EXP; i++) {
                if (!allowed[i] || used[i]) continue;
                if (best < 0 || bs[i] > bv) { best = i; bv = bs[i]; }
            }
            used[best] = true; sel[kk] = best; wv[kk] = sc[best]; wsum += sc[best];
        }
        const float inv = SCALING / (wsum + 1e-20f);
        #pragma unroll
        for (int kk = 0; kk < TOPK; kk++) {
            int ee = sel[kk];
            int slot = atomicAdd(&d_counts[ee], 1);
            d_tok[ee][slot] = t;
            d_wgt[ee][slot] = wv[kk] * inv;
        }
    }
}

// ---------------------------------------------------------------------------
// GEMM1: 512 threads (16 warps = 4m x 4n), CTA tile M=128 x N=64 x BK=32.
// Warp tile 32x16 per output (gate & up). Double-buffered smem.
// Stage: AH 0, AL 10240, GH 20480, GL 25600, UH 30720, UL 35840.
// ---------------------------------------------------------------------------
template<bool SHARED>
__global__ __launch_bounds__(512) void gemm1_mma(
    const float* __restrict__ x,
    const float* __restrict__ gateW,
    const float* __restrict__ upW)
{
    const int e  = SHARED ? 0 : blockIdx.z;
    const int ne = SHARED ? T_TOK : d_counts[e];
    const int m0 = blockIdx.y * 128;
    if (m0 >= ne) return;
    const int n0 = blockIdx.x * 64;

    extern __shared__ __align__(16) char dynsmem[];
    __shared__ int toks[128];

    const int tid = threadIdx.x, lane = tid & 31, wid = tid >> 5;
    const int wm = wid >> 2, wn = wid & 3;
    const uint32_t sb = smem_u32(dynsmem);

    if (tid < 128) {
        int r = m0 + tid;
        toks[tid] = SHARED ? r : (r < ne ? d_tok[e][r] : d_tok[e][0]);
    }
    __syncthreads();

    const float* gw = gateW + (SHARED ? 0 : (size_t)e * I_DIM * H_DIM);
    const float* uw = upW   + (SHARED ? 0 : (size_t)e * I_DIM * H_DIM);

    // loads: A 128x32 f32 -> 2 float4/thr; G/U 64x32 f32 -> 1 float4/thr each
    int arow[2], ach[2];
    uint32_t aOff[2];
    #pragma unroll
    for (int i = 0; i < 2; i++) {
        int t2 = tid + 512 * i; arow[i] = t2 >> 3; ach[i] = t2 & 7;
        aOff[i] = (uint32_t)(arow[i] * 80 + ach[i] * 8);
    }
    const int brow = tid >> 3, bch = tid & 7;
    const uint32_t bOff = (uint32_t)(brow * 80 + bch * 8);

    // precomputed stage-relative ldmatrix offsets
    uint32_t rAh[2], rAl[2];
    #pragma unroll
    for (int mi = 0; mi < 2; mi++) {
        rAh[mi] = ldrel(0u,      wm * 32 + mi * 16, lane);
        rAl[mi] = ldrel(10240u,  wm * 32 + mi * 16, lane);
    }
    const uint32_t rGh = ldrel(20480u, wn * 16, lane);
    const uint32_t rGl = ldrel(25600u, wn * 16, lane);
    const uint32_t rUh = ldrel(30720u, wn * 16, lane);
    const uint32_t rUl = ldrel(35840u, wn * 16, lane);

    float cg[2][2][4] = {}, cu[2][2][4] = {};
    float4 pa[2], pg, pu;

    #pragma unroll
    for (int i = 0; i < 2; i++)
        pa[i] = *(const float4*)(x + (size_t)toks[arow[i]] * H_DIM + ach[i] * 4);
    pg = *(const float4*)(gw + (size_t)(n0 + brow) * H_DIM + bch * 4);
    pu = *(const float4*)(uw + (size_t)(n0 + brow) * H_DIM + bch * 4);

    {
        const uint32_t st = sb;
        #pragma unroll
        for (int i = 0; i < 2; i++) {
            uint2 hw, lw; split4(pa[i], hw, lw);
            sts64(st + aOff[i], hw);
            sts64(st + 10240u + aOff[i], lw);
        }
        uint2 hw, lw;
        split4(pg, hw, lw);
        sts64(st + 20480u + bOff, hw);
        sts64(st + 25600u + bOff, lw);
        split4(pu, hw, lw);
        sts64(st + 30720u + bOff, hw);
        sts64(st + 35840u + bOff, lw);
    }
    __syncthreads();

    const int NK = H_DIM / 32;
    #pragma unroll 1
    for (int kt = 0; kt < NK; ++kt) {
        const uint32_t cur = sb + (uint32_t)(kt & 1) * STAGE_BYTES;
        const uint32_t nxt = sb + (uint32_t)((kt + 1) & 1) * STAGE_BYTES;
        const bool more = (kt + 1 < NK);

        if (more) {
            const int k0 = (kt + 1) * 32;
            #pragma unroll
            for (int i = 0; i < 2; i++)
                pa[i] = *(const float4*)(x + (size_t)toks[arow[i]] * H_DIM + k0 + ach[i] * 4);
            pg = *(const float4*)(gw + (size_t)(n0 + brow) * H_DIM + k0 + bch * 4);
            pu = *(const float4*)(uw + (size_t)(n0 + brow) * H_DIM + k0 + bch * 4);
        }

        #pragma unroll
        for (int kk = 0; kk < 2; ++kk) {
            const uint32_t kb = cur + (uint32_t)(kk * 32);
            uint32_t ah[2][4], al[2][4];
            #pragma unroll
            for (int mi = 0; mi < 2; mi++) {
                ldm_x4(kb + rAh[mi], ah[mi]);
                ldm_x4(kb + rAl[mi], al[mi]);
            }
            uint32_t gh[4], gl[4], uh[4], ul[4];
            ldm_x4(kb + rGh, gh);
            ldm_x4(kb + rGl, gl);
            ldm_x4(kb + rUh, uh);
            ldm_x4(kb + rUl, ul);

            #pragma unroll
            for (int mi = 0; mi < 2; mi++)
                #pragma unroll
                for (int ni = 0; ni < 2; ni++) {
                    mma_bf16(cg[mi][ni], ah[mi], gh[ni], gh[ni + 2]);
                    mma_bf16(cg[mi][ni], ah[mi], gl[ni], gl[ni + 2]);
                    mma_bf16(cg[mi][ni], al[mi], gh[ni], gh[ni + 2]);
                    mma_bf16(cu[mi][ni], ah[mi], uh[ni], uh[ni + 2]);
                    mma_bf16(cu[mi][ni], ah[mi], ul[ni], ul[ni + 2]);
                    mma_bf16(cu[mi][ni], al[mi], uh[ni], uh[ni + 2]);
                }
        }

        if (more) {
            #pragma unroll
            for (int i = 0; i < 2; i++) {
                uint2 hw, lw; split4(pa[i], hw, lw);
                sts64(nxt + aOff[i], hw);
                sts64(nxt + 10240u + aOff[i], lw);
            }
            uint2 hw, lw;
            split4(pg, hw, lw);
            sts64(nxt + 20480u + bOff, hw);
            sts64(nxt + 25600u + bOff, lw);
            split4(pu, hw, lw);
            sts64(nxt + 30720u + bOff, hw);
            sts64(nxt + 35840u + bOff, lw);
        }
        __syncthreads();
    }

    // epilogue: silu(g)*u -> bf16 hi/lo planes
    const int gr = lane >> 2, tc = (lane & 3) * 2;
    __nv_bfloat16* phi = SHARED ? &d_h1s_hi[0][0] : &d_h1_hi[e][0][0];
    __nv_bfloat16* plo = SHARED ? &d_h1s_lo[0][0] : &d_h1_lo[e][0][0];

    #pragma unroll
    for (int mi = 0; mi < 2; mi++)
        #pragma unroll
        for (int ni = 0; ni < 2; ni++) {
            int ncol = n0 + wn * 16 + ni * 8 + tc;
            #pragma unroll
            for (int half = 0; half < 2; half++) {
                int m = m0 + wm * 32 + mi * 16 + gr + half * 8;
                float g0 = cg[mi][ni][half * 2],     u0 = cu[mi][ni][half * 2];
                float g1 = cg[mi][ni][half * 2 + 1], u1 = cu[mi][ni][half * 2 + 1];
                float o0 = (g0 / (1.f + expf(-g0))) * u0;
                float o1 = (g1 / (1.f + expf(-g1))) * u1;
                uint32_t hw, lw; split2(o0, o1, hw, lw);
                *(uint32_t*)(phi + (size_t)m * I_DIM + ncol) = hw;
                *(uint32_t*)(plo + (size_t)m * I_DIM + ncol) = lw;
            }
        }
}

// ---------------------------------------------------------------------------
// GEMM2: 512 threads (16 warps = 4m x 4n), CTA tile M=128 x N=128 x BK=32.
// Warp tile 32x32. Stage: AH 0, AL 10240, BH 20480, BL 30720.
// ---------------------------------------------------------------------------
template<bool SHARED>
__global__ __launch_bounds__(512) void gemm2_mma(
    const float* __restrict__ downW,
    float* __restrict__ out)
{
    const int e  = SHARED ? 0 : blockIdx.z;
    const int ne = SHARED ? T_TOK : d_counts[e];
    const int m0 = blockIdx.y * 128;
    if (m0 >= ne) return;
    const int n0 = blockIdx.x * 128;

    extern __shared__ __align__(16) char dynsmem[];
    __shared__ int   toks[128];
    __shared__ float wgts[128];

    const int tid = threadIdx.x, lane = tid & 31, wid = tid >> 5;
    const int wm = wid >> 2, wn = wid & 3;
    const uint32_t sb = smem_u32(dynsmem);

    if (!SHARED && tid < 128) {
        int r = m0 + tid;
        toks[tid] = (r < ne) ? d_tok[e][r] : 0;
        wgts[tid] = (r < ne) ? d_wgt[e][r] : 0.f;
    }
    __syncthreads();

    const __nv_bfloat16* ahi = SHARED ? &d_h1s_hi[0][0] : &d_h1_hi[e][0][0];
    const __nv_bfloat16* alo = SHARED ? &d_h1s_lo[0][0] : &d_h1_lo[e][0][0];
    const float* dw = downW + (SHARED ? 0 : (size_t)e * H_DIM * I_DIM);

    // A: 128x32 bf16/plane, 1 uint4/thr; B: 128x32 f32, 2 float4/thr
    const int arow = tid >> 2, ach = tid & 3;
    const uint32_t aOff = (uint32_t)(arow * 80 + ach * 16);
    int brow[2], bch[2];
    uint32_t bOff[2];
    #pragma unroll
    for (int i = 0; i < 2; i++) {
        int t2 = tid + 512 * i; brow[i] = t2 >> 3; bch[i] = t2 & 7;
        bOff[i] = (uint32_t)(brow[i] * 80 + bch[i] * 8);
    }

    uint32_t rAh[2], rAl[2];
    #pragma unroll
    for (int mi = 0; mi < 2; mi++) {
        rAh[mi] = ldrel(0u,     wm * 32 + mi * 16, lane);
        rAl[mi] = ldrel(10240u, wm * 32 + mi * 16, lane);
    }
    const uint32_t rBh0 = ldrel(20480u, wn * 32,      lane);
    const uint32_t rBh1 = ldrel(20480u, wn * 32 + 16, lane);
    const uint32_t rBl0 = ldrel(30720u, wn * 32,      lane);
    const uint32_t rBl1 = ldrel(30720u, wn * 32 + 16, lane);

    float cd[2][4][4] = {};
    uint4  pah, pal;
    float4 pb[2];

    {
        size_t idx = (size_t)(m0 + arow) * I_DIM + ach * 8;
        pah = *(const uint4*)(ahi + idx);
        pal = *(const uint4*)(alo + idx);
    }
    #pragma unroll
    for (int i = 0; i < 2; i++)
        pb[i] = *(const float4*)(dw + (size_t)(n0 + brow[i]) * I_DIM + bch[i] * 4);

    {
        const uint32_t st = sb;
        sts128(st + aOff, pah);
        sts128(st + 10240u + aOff, pal);
        #pragma unroll
        for (int i = 0; i < 2; i++) {
            uint2 hw, lw; split4(pb[i], hw, lw);
            sts64(st + 20480u + bOff[i], hw);
            sts64(st + 30720u + bOff[i], lw);
        }
    }
    __syncthreads();

    const int NK = I_DIM / 32;
    #pragma unroll 1
    for (int kt = 0; kt < NK; ++kt) {
        const uint32_t cur = sb + (uint32_t)(kt & 1) * STAGE_BYTES;
        const uint32_t nxt = sb + (uint32_t)((kt + 1) & 1) * STAGE_BYTES;
        const bool more = (kt + 1 < NK);

        if (more) {
            const int k0 = (kt + 1) * 32;
            size_t idx = (size_t)(m0 + arow) * I_DIM + k0 + ach * 8;
            pah = *(const uint4*)(ahi + idx);
            pal = *(const uint4*)(alo + idx);
            #pragma unroll
            for (int i = 0; i < 2; i++)
                pb[i] = *(const float4*)(dw + (size_t)(n0 + brow[i]) * I_DIM + k0 + bch[i] * 4);
        }

        #pragma unroll
        for (int kk = 0; kk < 2; ++kk) {
            const uint32_t kb = cur + (uint32_t)(kk * 32);
            uint32_t ah[2][4], al[2][4];
            #pragma unroll
            for (int mi = 0; mi < 2; mi++) {
                ldm_x4(kb + rAh[mi], ah[mi]);
                ldm_x4(kb + rAl[mi], al[mi]);
            }
            uint32_t bh0[4], bh1[4], bl0[4], bl1[4];
            ldm_x4(kb + rBh0, bh0);
            ldm_x4(kb + rBh1, bh1);
            ldm_x4(kb + rBl0, bl0);
            ldm_x4(kb + rBl1, bl1);
            uint32_t bhs[4][2] = {{bh0[0],bh0[2]},{bh0[1],bh0[3]},{bh1[0],bh1[2]},{bh1[1],bh1[3]}};
            uint32_t bls[4][2] = {{bl0[0],bl0[2]},{bl0[1],bl0[3]},{bl1[0],bl1[2]},{bl1[1],bl1[3]}};

            #pragma unroll
            for (int mi = 0; mi < 2; mi++)
                #pragma unroll
                for (int ni = 0; ni < 4; ni++) {
                    mma_bf16(cd[mi][ni], ah[mi], bhs[ni][0], bhs[ni][1]);
                    mma_bf16(cd[mi][ni], ah[mi], bls[ni][0], bls[ni][1]);
                    mma_bf16(cd[mi][ni], al[mi], bhs[ni][0], bhs[ni][1]);
                }
        }

        if (more) {
            sts128(nxt + aOff, pah);
            sts128(nxt + 10240u + aOff, pal);
            #pragma unroll
            for (int i = 0; i < 2; i++) {
                uint2 hw, lw; split4(pb[i], hw, lw);
                sts64(nxt + 20480u + bOff[i], hw);
                sts64(nxt + 30720u + bOff[i], lw);
            }
        }
        __syncthreads();
    }

    // epilogue
    const int gr = lane >> 2, tc = (lane & 3) * 2;
    #pragma unroll
    for (int mi = 0; mi < 2; mi++)
        #pragma unroll
        for (int ni = 0; ni < 4; ni++) {
            int ncol = n0 + wn * 32 + ni * 8 + tc;
            #pragma unroll
            for (int half = 0; half < 2; half++) {
                int mloc = wm * 32 + mi * 16 + gr + half * 8;
                float v0 = cd[mi][ni][half * 2];
                float v1 = cd[mi][ni][half * 2 + 1];
                if (SHARED) {
                    int t = m0 + mloc;
                    float2 v = {v0, v1};
                    *(float2*)(out + (size_t)t * H_DIM + ncol) = v;
                } else {
                    if (m0 + mloc < ne) {
                        int   t = toks[mloc];
                        float w = wgts[mloc];
                        float* op = out + (size_t)t * H_DIM + ncol;
                        atomicAdd(op,     w * v0);
                        atomicAdd(op + 1, w * v1);
                    }
                }
            }
        }
}

// ---------------------------------------------------------------------------
// Launch
// ---------------------------------------------------------------------------
extern "C" void kernel_launch(void* const* d_in, const int* in_sizes, int n_in,
                              void* d_out, int out_size)
{
    const float* x  = (const float*)d_in[0];
    const float* gw = (const float*)d_in[1];
    const float* eb = (const float*)d_in[2];
    const float* gp = (const float*)d_in[3];
    const float* up = (const float*)d_in[4];
    const float* dp = (const float*)d_in[5];
    const float* sg = (const float*)d_in[6];
    const float* su = (const float*)d_in[7];
    const float* sd = (const float*)d_in[8];
    float* out = (float*)d_out;

    static bool attr_set = false;
    if (!attr_set) {
        cudaFuncSetAttribute((const void*)gemm1_mma<false>, cudaFuncAttributeMaxDynamicSharedMemorySize, SMEM_DYN);
        cudaFuncSetAttribute((const void*)gemm1_mma<true>,  cudaFuncAttributeMaxDynamicSharedMemorySize, SMEM_DYN);
        cudaFuncSetAttribute((const void*)gemm2_mma<false>, cudaFuncAttributeMaxDynamicSharedMemorySize, SMEM_DYN);
        cudaFuncSetAttribute((const void*)gemm2_mma<true>,  cudaFuncAttributeMaxDynamicSharedMemorySize, SMEM_DYN);
        attr_set = true;
    }

    zero_counts_kernel<<<1, 32>>>();
    route_kernel<<<T_TOK, 256>>>(x, gw, eb);

    gemm1_mma<false><<<dim3(I_DIM / 64, T_TOK / 128, N_EXP), 512, SMEM_DYN>>>(x, gp, up);
    gemm1_mma<true> <<<dim3(I_DIM / 64, T_TOK / 128, 1),     512, SMEM_DYN>>>(x, sg, su);

    gemm2_mma<true> <<<dim3(H_DIM / 128, T_TOK / 128, 1),     512, SMEM_DYN>>>(sd, out);
    gemm2_mma<false><<<dim3(H_DIM / 128, T_TOK / 128, N_EXP), 512, SMEM_DYN>>>(dp, out);
}